// round 14
// baseline (speedup 1.0000x reference)
#include <cuda_runtime.h>
#include <cuda_bf16.h>
#include <cstdint>

// Problem: T=256, B=64, E=512, H=512, HD=256, L=2, K=7
#define NEG_ -10000.0f

// packed f32x2 helpers (sm_103a)
#define FMA2(d, a, b) asm("fma.rn.f32x2 %0, %1, %2, %0;" : "+l"(d) : "l"(a), "l"(b))
#define PACK2(out, v) asm("mov.b64 %0, {%1, %1};" : "=l"(out) : "r"(__float_as_uint(v)))
#define UNPK2(lo, hi, in) asm("mov.b64 {%0, %1}, %2;" : "=r"(lo), "=r"(hi) : "l"(in))

// ---------------- device scratch (no cudaMalloc allowed) ----------------
__device__ float g_x [16384*512];   // embedded input (layer0 GEMM A)
__device__ float g_y0[16384*512];   // layer0 hidden output [m][dir*256+hd]
__device__ float g_y1[16384*512];   // layer1 hidden output
__device__ float g_xg[16384*2048];  // input-gate preacts [m][dir*1024 + gate*256 + hd]
__device__ float g_feats[16384*7];

// ---------------- LSTM smem layout (floats) ----------------
//  W_s   : 128 rows x 276   (row = gate*32+hd; K-half0 at cols 0..127, half1 at 144..271)
//  h_in  : [2 parity][8 src_rank][8 b][32 hd]  slot stride 268 (1072B, 16B-aligned)
//          within slot: col = b*32 + (hd ^ s(b)), s(b) = (((b>>1)&3)<<3) ^ ((b&1)<<2)
//  stg   : [2 parity][256]  contiguous 1KB bulk-copy source, same swizzled order
#define GSTR   276
#define KSOFF  144
#define W_FLOATS   (128*GSTR)                 /* 35328 */
#define HIN_OFF    W_FLOATS
#define HIN_SLOT   268
#define HIN_PAR    (8*HIN_SLOT)               /* 2144 */
#define STG_OFF    (HIN_OFF + 2*HIN_PAR)      /* 39616 */
#define MBAR_OFF_F (STG_OFF + 2*256)          /* 40128 */
#define LSTM_SMEM_BYTES ((MBAR_OFF_F + 4) * 4)  /* 160528 */
#define VIT_SMEM_BYTES  (256*64*4)              /* 65536  */

// ============================================================
// 1) Embedding gather
// ============================================================
__global__ void __launch_bounds__(256) embed_kernel(const int* __restrict__ sent,
                                                    const float* __restrict__ emb)
{
    int gw   = (blockIdx.x * 256 + threadIdx.x) >> 5;
    int lane = threadIdx.x & 31;
    int nw   = gridDim.x * 8;
    for (int row = gw; row < 16384; row += nw) {
        int tok = sent[row];
        const float4* s = (const float4*)(emb + (size_t)tok * 512);
        float4*       d = (float4*)(g_x + (size_t)row * 512);
        #pragma unroll
        for (int i = 0; i < 4; i++) d[lane + i * 32] = s[lane + i * 32];
    }
}

// ============================================================
// 2) GEMM: g_xg[m][n] = A[m][:] . W[n][:] + b1[n] + b2[n]
// ============================================================
__global__ void __launch_bounds__(256, 2)
gemm_kernel(const float* __restrict__ W, const float* __restrict__ b1,
            const float* __restrict__ b2, int layer)
{
    const float* A = layer ? g_y0 : g_x;
    __shared__ __align__(16) float As[2][8][132];
    __shared__ __align__(16) float Bs[2][8][132];

    int tid  = threadIdx.x;
    int m0   = blockIdx.y * 128;
    int n0   = blockIdx.x * 128;
    int lrow = tid >> 1;            // 0..127
    int kc   = (tid & 1) * 4;       // 0 or 4
    const float* Ap = A + (size_t)(m0 + lrow) * 512 + kc;
    const float* Wp = W + (size_t)(n0 + lrow) * 512 + kc;
    int tr = tid >> 4;              // 0..15
    int tc = tid & 15;              // 0..15

    unsigned long long acc2[8][4];
    #pragma unroll
    for (int i = 0; i < 8; i++)
        #pragma unroll
        for (int j = 0; j < 4; j++) acc2[i][j] = 0ull;

    {
        float4 pa = *(const float4*)Ap;
        float4 pb = *(const float4*)Wp;
        As[0][kc + 0][lrow] = pa.x; As[0][kc + 1][lrow] = pa.y;
        As[0][kc + 2][lrow] = pa.z; As[0][kc + 3][lrow] = pa.w;
        Bs[0][kc + 0][lrow] = pb.x; Bs[0][kc + 1][lrow] = pb.y;
        Bs[0][kc + 2][lrow] = pb.z; Bs[0][kc + 3][lrow] = pb.w;
    }
    __syncthreads();

    for (int kt = 0; kt < 64; kt++) {
        int cur = kt & 1;
        float4 na, nb;
        if (kt < 63) {
            na = *(const float4*)(Ap + (kt + 1) * 8);
            nb = *(const float4*)(Wp + (kt + 1) * 8);
        }
        #pragma unroll
        for (int kk = 0; kk < 8; kk++) {
            float4 alo = *(const float4*)&As[cur][kk][tr * 4];
            float4 ahi = *(const float4*)&As[cur][kk][64 + tr * 4];
            ulonglong2 bl = *(const ulonglong2*)&Bs[cur][kk][tc * 4];
            ulonglong2 bh = *(const ulonglong2*)&Bs[cur][kk][64 + tc * 4];
            float av[8] = {alo.x, alo.y, alo.z, alo.w, ahi.x, ahi.y, ahi.z, ahi.w};
            #pragma unroll
            for (int i = 0; i < 8; i++) {
                unsigned long long a2;
                PACK2(a2, av[i]);
                FMA2(acc2[i][0], a2, bl.x);
                FMA2(acc2[i][1], a2, bl.y);
                FMA2(acc2[i][2], a2, bh.x);
                FMA2(acc2[i][3], a2, bh.y);
            }
        }
        if (kt < 63) {
            int nxt = cur ^ 1;
            As[nxt][kc + 0][lrow] = na.x; As[nxt][kc + 1][lrow] = na.y;
            As[nxt][kc + 2][lrow] = na.z; As[nxt][kc + 3][lrow] = na.w;
            Bs[nxt][kc + 0][lrow] = nb.x; Bs[nxt][kc + 1][lrow] = nb.y;
            Bs[nxt][kc + 2][lrow] = nb.z; Bs[nxt][kc + 3][lrow] = nb.w;
            __syncthreads();
        }
    }

    #pragma unroll
    for (int i = 0; i < 8; i++) {
        int r = m0 + ((i < 4) ? (tr * 4 + i) : (64 + tr * 4 + i - 4));
        #pragma unroll
        for (int jh = 0; jh < 2; jh++) {
            int cb = n0 + jh * 64 + tc * 4;
            unsigned int u0, u1, u2, u3;
            UNPK2(u0, u1, acc2[i][jh * 2 + 0]);
            UNPK2(u2, u3, acc2[i][jh * 2 + 1]);
            float4 o;
            o.x = __uint_as_float(u0) + b1[cb + 0] + b2[cb + 0];
            o.y = __uint_as_float(u1) + b1[cb + 1] + b2[cb + 1];
            o.z = __uint_as_float(u2) + b1[cb + 2] + b2[cb + 2];
            o.w = __uint_as_float(u3) + b1[cb + 3] + b2[cb + 3];
            *(float4*)(g_xg + (size_t)r * 2048 + cb) = o;
        }
    }
}

// ============================================================
// 3) LSTM recurrence (one layer, both dirs).
//    128 CTAs = 16 clusters of 8; cluster = (dir, 8-batch chunk);
//    CTA rank r owns hd in [r*32, r*32+32).
//    Exchange: h values staged into a contiguous 1KB smem buffer,
//    then warp w's lane0 issues ONE 1KB cp.async.bulk (S2S cluster)
//    to rank w with complete_tx on the remote tx-mbarrier
//    (expect_tx 8192/step). 8 fabric transactions/CTA/step instead
//    of 2048 scalar st.async. Buffers parity-double-buffered; reuse
//    safety follows from the mbarrier phase dependency chain.
// ============================================================
__device__ __forceinline__ float sigf(float x) { return 1.0f / (1.0f + __expf(-x)); }

__global__ void __cluster_dims__(8, 1, 1) __launch_bounds__(256, 1)
lstm_kernel(const float* __restrict__ w_hh,   // layer base: [2][1024][256]
            const float* __restrict__ h0,     // [4][64][256]
            const float* __restrict__ c0,
            int layer)
{
    extern __shared__ float smem[];
    float* W_s  = smem;
    float* h_in = smem + HIN_OFF;
    float* stg  = smem + STG_OFF;

    float* y = layer ? g_y1 : g_y0;

    int bx  = blockIdx.x;
    int cid = bx >> 3;                   // 0..15
    int r   = bx & 7;                    // hd-chunk rank
    int dir = cid & 1;
    int bc  = cid >> 1;                  // batch chunk 0..7
    int tid = threadIdx.x;
    int hd  = tid >> 3;                  // 0..31
    int bp  = (tid >> 1) & 3;            // batch pair 0..3
    int ks  = tid & 1;                   // K-half
    int wrp = tid >> 5;                  // warp index == target rank for bulk
    int hd_g = r * 32 + hd;
    int b_ep = bp * 2 + ks;              // epilogue batch within chunk
    int b_g  = bc * 8 + b_ep;

    // ---- load W_hh slice into split-row layout (unchanged from R12) ----
    const float* Wd = w_hh + (size_t)dir * 1024 * 256;
    for (int i = tid; i < 128 * 64; i += 256) {
        int row = i >> 6, q = i & 63;
        int grow = (row >> 5) * 256 + r * 32 + (row & 31);
        float4 v = *(const float4*)(Wd + (size_t)grow * 256 + q * 4);
        int col = (q < 32) ? q * 4 : KSOFF + (q - 32) * 4;
        *(float4*)(W_s + row * GSTR + col) = v;
    }
    // ---- initial h (parity 0) into swizzled slot layout ----
    const float* h0d = h0 + ((size_t)(2 * layer + dir) * 64 + bc * 8) * 256;
    for (int i = tid; i < 2048; i += 256) {
        int b = i >> 8, k = i & 255;
        int rB = k >> 5, hl = k & 31;
        int sw = (((b >> 1) & 3) << 3) ^ ((b & 1) << 2);
        h_in[rB * HIN_SLOT + b * 32 + (hl ^ sw)] = h0d[b * 256 + k];
    }
    float c = c0[((size_t)(2 * layer + dir) * 64 + b_g) * 256 + hd_g];

    // local tx-mbarrier
    uint32_t smem_u32 = (uint32_t)__cvta_generic_to_shared(smem);
    uint32_t mbar_l   = smem_u32 + MBAR_OFF_F * 4;
    if (tid == 0)
        asm volatile("mbarrier.init.shared.b64 [%0], 1;" :: "r"(mbar_l) : "memory");
    __syncthreads();
    asm volatile("barrier.cluster.arrive.aligned;" ::: "memory");
    asm volatile("barrier.cluster.wait.aligned;"   ::: "memory");

    // per-warp remote addresses: our slot (src_rank = r) in rank wrp's h_in
    uint32_t rmb = 0, dstP0 = 0, dstP1 = 0;
    if ((tid & 31) == 0) {
        uint32_t d0 = smem_u32 + (uint32_t)((HIN_OFF + 0 * HIN_PAR + r * HIN_SLOT) * 4);
        uint32_t d1 = smem_u32 + (uint32_t)((HIN_OFF + 1 * HIN_PAR + r * HIN_SLOT) * 4);
        asm("mapa.shared::cluster.u32 %0, %1, %2;" : "=r"(rmb)   : "r"(mbar_l), "r"(wrp));
        asm("mapa.shared::cluster.u32 %0, %1, %2;" : "=r"(dstP0) : "r"(d0),     "r"(wrp));
        asm("mapa.shared::cluster.u32 %0, %1, %2;" : "=r"(dstP1) : "r"(d1),     "r"(wrp));
    }

    const float* w0r = W_s + (hd)      * GSTR + ks * KSOFF;
    const float* w1r = W_s + (32 + hd) * GSTR + ks * KSOFF;
    const float* w2r = W_s + (64 + hd) * GSTR + ks * KSOFF;
    const float* w3r = W_s + (96 + hd) * GSTR + ks * KSOFF;
    const float* hbse = h_in + (ks * 4) * HIN_SLOT + (bp * 2) * 32;
    int sw0 = bp << 3;                                 // swizzle for even batch
    int stg_col = b_ep * 32 + (hd ^ (sw0 ^ (ks << 2)));  // this thread's staging slot

    for (int s = 0; s < 256; s++) {
        int t  = dir ? (255 - s) : s;
        int p  = s & 1;
        int wp = p ^ 1;

        // arm this step's phase: 1 arrive + 8192 tx bytes expected
        if (tid == 0 && s < 255)
            asm volatile("mbarrier.arrive.expect_tx.shared.b64 _, [%0], 8192;"
                         :: "r"(mbar_l) : "memory");

        // prefetch input-gate preacts for epilogue batch
        size_t xb = ((size_t)t * 64 + b_g) * 2048 + (size_t)dir * 1024 + hd_g;
        float xg0 = g_xg[xb];
        float xg1 = g_xg[xb + 256];
        float xg2 = g_xg[xb + 512];
        float xg3 = g_xg[xb + 768];

        const float* hp = hbse + p * HIN_PAR;

        unsigned long long a00 = 0, a01 = 0, a10 = 0, a11 = 0;
        unsigned long long a20 = 0, a21 = 0, a30 = 0, a31 = 0;
        #pragma unroll
        for (int rr = 0; rr < 4; rr++) {
            const float* hR0 = hp + rr * HIN_SLOT;
            const float* hR1 = hR0 + 32;
            const float* wo0 = w0r + rr * 32;
            const float* wo1 = w1r + rr * 32;
            const float* wo2 = w2r + rr * 32;
            const float* wo3 = w3r + rr * 32;
            #pragma unroll
            for (int j4 = 0; j4 < 8; j4++) {
                int c0 = (j4 * 4) ^ sw0;
                ulonglong2 h0v = *(const ulonglong2*)(hR0 + c0);
                ulonglong2 h1v = *(const ulonglong2*)(hR1 + (c0 ^ 4));
                ulonglong2 w0v = *(const ulonglong2*)(wo0 + j4 * 4);
                ulonglong2 w1v = *(const ulonglong2*)(wo1 + j4 * 4);
                ulonglong2 w2v = *(const ulonglong2*)(wo2 + j4 * 4);
                ulonglong2 w3v = *(const ulonglong2*)(wo3 + j4 * 4);
                FMA2(a00, w0v.x, h0v.x); FMA2(a00, w0v.y, h0v.y);
                FMA2(a01, w0v.x, h1v.x); FMA2(a01, w0v.y, h1v.y);
                FMA2(a10, w1v.x, h0v.x); FMA2(a10, w1v.y, h0v.y);
                FMA2(a11, w1v.x, h1v.x); FMA2(a11, w1v.y, h1v.y);
                FMA2(a20, w2v.x, h0v.x); FMA2(a20, w2v.y, h0v.y);
                FMA2(a21, w2v.x, h1v.x); FMA2(a21, w2v.y, h1v.y);
                FMA2(a30, w3v.x, h0v.x); FMA2(a30, w3v.y, h0v.y);
                FMA2(a31, w3v.x, h1v.x); FMA2(a31, w3v.y, h1v.y);
            }
        }

        // fold f32x2 halves, then K-half reduce with partner lane (ks^1)
        float d0, d1, d2, d3;
        {
            unsigned int lo, hi; float v0, v1;
            UNPK2(lo, hi, a00); v0 = __uint_as_float(lo) + __uint_as_float(hi);
            UNPK2(lo, hi, a01); v1 = __uint_as_float(lo) + __uint_as_float(hi);
            v0 += __shfl_xor_sync(0xFFFFFFFFu, v0, 1);
            v1 += __shfl_xor_sync(0xFFFFFFFFu, v1, 1);
            d0 = ks ? v1 : v0;
            UNPK2(lo, hi, a10); v0 = __uint_as_float(lo) + __uint_as_float(hi);
            UNPK2(lo, hi, a11); v1 = __uint_as_float(lo) + __uint_as_float(hi);
            v0 += __shfl_xor_sync(0xFFFFFFFFu, v0, 1);
            v1 += __shfl_xor_sync(0xFFFFFFFFu, v1, 1);
            d1 = ks ? v1 : v0;
            UNPK2(lo, hi, a20); v0 = __uint_as_float(lo) + __uint_as_float(hi);
            UNPK2(lo, hi, a21); v1 = __uint_as_float(lo) + __uint_as_float(hi);
            v0 += __shfl_xor_sync(0xFFFFFFFFu, v0, 1);
            v1 += __shfl_xor_sync(0xFFFFFFFFu, v1, 1);
            d2 = ks ? v1 : v0;
            UNPK2(lo, hi, a30); v0 = __uint_as_float(lo) + __uint_as_float(hi);
            UNPK2(lo, hi, a31); v1 = __uint_as_float(lo) + __uint_as_float(hi);
            v0 += __shfl_xor_sync(0xFFFFFFFFu, v0, 1);
            v1 += __shfl_xor_sync(0xFFFFFFFFu, v1, 1);
            d3 = ks ? v1 : v0;
        }

        float ig = sigf(d0 + xg0);
        float fg = sigf(d1 + xg1);
        float gg = tanhf(d2 + xg2);
        float og = sigf(d3 + xg3);
        c = fg * c + ig * gg;
        float h = og * tanhf(c);

        // layer output (fire-and-forget)
        y[((size_t)t * 64 + b_g) * 512 + (size_t)dir * 256 + hd_g] = h;

        if (s < 255) {
            // stage h into this parity's contiguous 1KB buffer
            stg[wp * 256 + stg_col] = h;
            __syncthreads();

            // one 1KB bulk copy per rank (warp w -> rank w), complete_tx remote
            if ((tid & 31) == 0) {
                asm volatile("fence.proxy.async.shared::cta;" ::: "memory");
                uint32_t src = smem_u32 + (uint32_t)((STG_OFF + wp * 256) * 4);
                uint32_t dst = wp ? dstP1 : dstP0;
                asm volatile(
                    "cp.async.bulk.shared::cluster.shared::cta.mbarrier::complete_tx::bytes "
                    "[%0], [%1], %2, [%3];"
                    :: "r"(dst), "r"(src), "r"(1024), "r"(rmb) : "memory");
            }

            // wait for this step's phase (all 8KB delivered), acquire cluster
            unsigned int par = (unsigned int)(s & 1);
            asm volatile(
                "{\n\t"
                ".reg .pred P;\n\t"
                "WAIT_%=:\n\t"
                "mbarrier.try_wait.parity.acquire.cluster.shared::cta.b64 P, [%0], %1, 0x989680;\n\t"
                "@!P bra WAIT_%=;\n\t"
                "}"
                :: "r"(mbar_l), "r"(par) : "memory");
        }
    }
}

// ============================================================
// 4) hidden2tag
// ============================================================
__global__ void __launch_bounds__(256)
feats_kernel(const float* __restrict__ w_out, const float* __restrict__ b_out)
{
    __shared__ float ws[7 * 512];
    __shared__ float bs[7];
    int tid = threadIdx.x;
    for (int i = tid; i < 3584; i += 256) ws[i] = w_out[i];
    if (tid < 7) bs[tid] = b_out[tid];
    __syncthreads();

    int gw   = (blockIdx.x * 256 + tid) >> 5;
    int lane = tid & 31;
    int nw   = gridDim.x * 8;
    for (int m = gw; m < 16384; m += nw) {
        const float4* y4 = (const float4*)(g_y1 + (size_t)m * 512);
        float acc[7] = {0, 0, 0, 0, 0, 0, 0};
        #pragma unroll
        for (int q = 0; q < 4; q++) {
            int k4 = q * 32 + lane;
            float4 yv = y4[k4];
            #pragma unroll
            for (int tg = 0; tg < 7; tg++) {
                float4 wv = *(const float4*)(ws + tg * 512 + k4 * 4);
                acc[tg] += yv.x * wv.x + yv.y * wv.y + yv.z * wv.z + yv.w * wv.w;
            }
        }
        #pragma unroll
        for (int tg = 0; tg < 7; tg++) {
            #pragma unroll
            for (int off = 16; off; off >>= 1)
                acc[tg] += __shfl_xor_sync(0xFFFFFFFFu, acc[tg], off);
        }
        float v = acc[0];
        #pragma unroll
        for (int tg = 1; tg < 7; tg++) if (lane == tg) v = acc[tg];
        if (lane < 7) g_feats[m * 7 + lane] = v + bs[lane];
    }
}

// ============================================================
// 5) Viterbi: 1 CTA, thread = batch; packed backpointers in smem.
//    out = [path as float (B*T)] ++ [score (B)]
// ============================================================
__global__ void __launch_bounds__(64)
viterbi_kernel(const float* __restrict__ trans, float* __restrict__ out)
{
    extern __shared__ unsigned int bp_s[];   // [256][64]
    __shared__ float tr[49];
    int b = threadIdx.x;
    if (b < 49) tr[b] = trans[b];
    __syncthreads();

    float v[7];
    #pragma unroll
    for (int k = 0; k < 7; k++) v[k] = (k == 5) ? 0.0f : NEG_;  // START=5

    for (int t = 0; t < 256; t++) {
        const float* f = g_feats + ((size_t)t * 64 + b) * 7;
        float fv[7];
        #pragma unroll
        for (int k = 0; k < 7; k++) fv[k] = f[k];

        unsigned int word = 0;
        float nv[7];
        #pragma unroll
        for (int nx = 0; nx < 7; nx++) {
            float best = v[0] + tr[nx * 7 + 0];
            int arg = 0;
            #pragma unroll
            for (int pv = 1; pv < 7; pv++) {
                float sc = v[pv] + tr[nx * 7 + pv];
                if (sc > best) { best = sc; arg = pv; }
            }
            nv[nx] = best + fv[nx];
            word |= ((unsigned int)arg) << (3 * nx);
        }
        #pragma unroll
        for (int k = 0; k < 7; k++) v[k] = nv[k];
        bp_s[t * 64 + b] = word;
    }

    float best = v[0] + tr[6 * 7 + 0];
    int last = 0;
    #pragma unroll
    for (int k = 1; k < 7; k++) {
        float sc = v[k] + tr[6 * 7 + k];
        if (sc > best) { best = sc; last = k; }
    }
    out[16384 + b] = best;

    int tag = last;
    out[(size_t)b * 256 + 255] = (float)tag;
    for (int t = 254; t >= 0; t--) {
        unsigned int w = bp_s[(t + 1) * 64 + b];
        tag = (int)((w >> (3 * tag)) & 7u);
        out[(size_t)b * 256 + t] = (float)tag;
    }
}

// ============================================================
// launcher
// ============================================================
extern "C" void kernel_launch(void* const* d_in, const int* in_sizes, int n_in,
                              void* d_out, int out_size)
{
    (void)in_sizes; (void)n_in; (void)out_size;
    const int*   sent  = (const int*)  d_in[0];
    const float* emb   = (const float*)d_in[1];
    const float* w_ih  = (const float*)d_in[2];
    const float* w_hh  = (const float*)d_in[3];
    const float* b_ih  = (const float*)d_in[4];
    const float* b_hh  = (const float*)d_in[5];
    const float* w_out = (const float*)d_in[6];
    const float* b_out = (const float*)d_in[7];
    const float* trans = (const float*)d_in[8];
    const float* h0    = (const float*)d_in[9];
    const float* c0    = (const float*)d_in[10];
    float* out = (float*)d_out;

    cudaFuncSetAttribute(lstm_kernel, cudaFuncAttributeMaxDynamicSharedMemorySize,
                         LSTM_SMEM_BYTES);
    cudaFuncSetAttribute(viterbi_kernel, cudaFuncAttributeMaxDynamicSharedMemorySize,
                         VIT_SMEM_BYTES);

    embed_kernel<<<256, 256>>>(sent, emb);
    for (int l = 0; l < 2; l++) {
        gemm_kernel<<<dim3(16, 128), 256>>>(w_ih + (size_t)l * 2048 * 512,
                                            b_ih + l * 2048,
                                            b_hh + l * 2048, l);
        lstm_kernel<<<128, 256, LSTM_SMEM_BYTES>>>(w_hh + (size_t)l * 2 * 1024 * 256,
                                                   h0, c0, l);
    }
    feats_kernel<<<256, 256>>>(w_out, b_out);
    viterbi_kernel<<<1, 64, VIT_SMEM_BYTES>>>(trans, out);
}

// round 17
// speedup vs baseline: 1.4995x; 1.4995x over previous
#include <cuda_runtime.h>
#include <cuda_bf16.h>
#include <cstdint>

// Problem: T=256, B=64, E=512, H=512, HD=256, L=2, K=7
#define NEG_ -10000.0f

// packed f32x2 helpers (sm_103a)
#define FMA2(d, a, b) asm("fma.rn.f32x2 %0, %1, %2, %0;" : "+l"(d) : "l"(a), "l"(b))
#define PACK2(out, v) asm("mov.b64 %0, {%1, %1};" : "=l"(out) : "r"(__float_as_uint(v)))
#define UNPK2(lo, hi, in) asm("mov.b64 {%0, %1}, %2;" : "=r"(lo), "=r"(hi) : "l"(in))

// ---------------- device scratch (no cudaMalloc allowed) ----------------
__device__ float g_x [16384*512];   // embedded input (layer0 GEMM A)
__device__ float g_y0[16384*512];   // layer0 hidden output [m][dir*256+hd]
__device__ float g_y1[16384*512];   // layer1 hidden output
__device__ float g_xg[16384*2048];  // input-gate preacts [m][dir*1024 + gate*256 + hd]
__device__ float g_feats[16384*7];

// ---------------- LSTM smem layout (floats) ----------------
//  h_in : [2 parity][8 b][260]      (row pad 260; reads are warp-broadcast)
//  scr  : [8 b][32 hd][36]          (4g x 8kc partials + pad, 16B-aligned rows)
#define HROW   260
#define HPARF  (8*HROW)              /* 2080 */
#define SCR_OFF (2*HPARF)            /* 4160 */
#define SCRROW  36
#define MBAR_F  (SCR_OFF + 8*32*SCRROW)   /* 4160+9216 = 13376 */
#define LSTM_SMEM_BYTES ((MBAR_F + 4) * 4)  /* 53520 */
#define VIT_SMEM_BYTES  (256*64*4)          /* 65536 */

// ============================================================
// 1) Embedding gather
// ============================================================
__global__ void __launch_bounds__(256) embed_kernel(const int* __restrict__ sent,
                                                    const float* __restrict__ emb)
{
    int gw   = (blockIdx.x * 256 + threadIdx.x) >> 5;
    int lane = threadIdx.x & 31;
    int nw   = gridDim.x * 8;
    for (int row = gw; row < 16384; row += nw) {
        int tok = sent[row];
        const float4* s = (const float4*)(emb + (size_t)tok * 512);
        float4*       d = (float4*)(g_x + (size_t)row * 512);
        #pragma unroll
        for (int i = 0; i < 4; i++) d[lane + i * 32] = s[lane + i * 32];
    }
}

// ============================================================
// 2) GEMM: g_xg[m][n] = A[m][:] . W[n][:] + b1[n] + b2[n]
// ============================================================
__global__ void __launch_bounds__(256, 2)
gemm_kernel(const float* __restrict__ W, const float* __restrict__ b1,
            const float* __restrict__ b2, int layer)
{
    const float* A = layer ? g_y0 : g_x;
    __shared__ __align__(16) float As[2][8][132];
    __shared__ __align__(16) float Bs[2][8][132];

    int tid  = threadIdx.x;
    int m0   = blockIdx.y * 128;
    int n0   = blockIdx.x * 128;
    int lrow = tid >> 1;            // 0..127
    int kc   = (tid & 1) * 4;       // 0 or 4
    const float* Ap = A + (size_t)(m0 + lrow) * 512 + kc;
    const float* Wp = W + (size_t)(n0 + lrow) * 512 + kc;
    int tr = tid >> 4;              // 0..15
    int tc = tid & 15;              // 0..15

    unsigned long long acc2[8][4];
    #pragma unroll
    for (int i = 0; i < 8; i++)
        #pragma unroll
        for (int j = 0; j < 4; j++) acc2[i][j] = 0ull;

    {
        float4 pa = *(const float4*)Ap;
        float4 pb = *(const float4*)Wp;
        As[0][kc + 0][lrow] = pa.x; As[0][kc + 1][lrow] = pa.y;
        As[0][kc + 2][lrow] = pa.z; As[0][kc + 3][lrow] = pa.w;
        Bs[0][kc + 0][lrow] = pb.x; Bs[0][kc + 1][lrow] = pb.y;
        Bs[0][kc + 2][lrow] = pb.z; Bs[0][kc + 3][lrow] = pb.w;
    }
    __syncthreads();

    for (int kt = 0; kt < 64; kt++) {
        int cur = kt & 1;
        float4 na, nb;
        if (kt < 63) {
            na = *(const float4*)(Ap + (kt + 1) * 8);
            nb = *(const float4*)(Wp + (kt + 1) * 8);
        }
        #pragma unroll
        for (int kk = 0; kk < 8; kk++) {
            float4 alo = *(const float4*)&As[cur][kk][tr * 4];
            float4 ahi = *(const float4*)&As[cur][kk][64 + tr * 4];
            ulonglong2 bl = *(const ulonglong2*)&Bs[cur][kk][tc * 4];
            ulonglong2 bh = *(const ulonglong2*)&Bs[cur][kk][64 + tc * 4];
            float av[8] = {alo.x, alo.y, alo.z, alo.w, ahi.x, ahi.y, ahi.z, ahi.w};
            #pragma unroll
            for (int i = 0; i < 8; i++) {
                unsigned long long a2;
                PACK2(a2, av[i]);
                FMA2(acc2[i][0], a2, bl.x);
                FMA2(acc2[i][1], a2, bl.y);
                FMA2(acc2[i][2], a2, bh.x);
                FMA2(acc2[i][3], a2, bh.y);
            }
        }
        if (kt < 63) {
            int nxt = cur ^ 1;
            As[nxt][kc + 0][lrow] = na.x; As[nxt][kc + 1][lrow] = na.y;
            As[nxt][kc + 2][lrow] = na.z; As[nxt][kc + 3][lrow] = na.w;
            Bs[nxt][kc + 0][lrow] = nb.x; Bs[nxt][kc + 1][lrow] = nb.y;
            Bs[nxt][kc + 2][lrow] = nb.z; Bs[nxt][kc + 3][lrow] = nb.w;
            __syncthreads();
        }
    }

    #pragma unroll
    for (int i = 0; i < 8; i++) {
        int r = m0 + ((i < 4) ? (tr * 4 + i) : (64 + tr * 4 + i - 4));
        #pragma unroll
        for (int jh = 0; jh < 2; jh++) {
            int cb = n0 + jh * 64 + tc * 4;
            unsigned int u0, u1, u2, u3;
            UNPK2(u0, u1, acc2[i][jh * 2 + 0]);
            UNPK2(u2, u3, acc2[i][jh * 2 + 1]);
            float4 o;
            o.x = __uint_as_float(u0) + b1[cb + 0] + b2[cb + 0];
            o.y = __uint_as_float(u1) + b1[cb + 1] + b2[cb + 1];
            o.z = __uint_as_float(u2) + b1[cb + 2] + b2[cb + 2];
            o.w = __uint_as_float(u3) + b1[cb + 3] + b2[cb + 3];
            *(float4*)(g_xg + (size_t)r * 2048 + cb) = o;
        }
    }
}

// ============================================================
// 3) LSTM recurrence (one layer, both dirs).
//    128 CTAs = 16 clusters of 8; cluster = (dir, 8-batch chunk);
//    CTA rank r owns hd in [r*32, r*32+32).
//    Thread = (warp kc 0..7 = K-chunk, lane hd 0..31). W block
//    (4 gates x 32 K = 128 floats) lives in REGISTERS for all 256
//    steps -> zero W smem traffic. h reads are warp-broadcast LDS.
//    Cross-kc reduction through padded smem scratch (one
//    __syncthreads). Epilogue thread = (b = warp, hd = lane).
//    Exchange = R12 scalar st.async + tx-mbarrier (proven best).
// ============================================================
__device__ __forceinline__ float sigf(float x) { return 1.0f / (1.0f + __expf(-x)); }

__global__ void __cluster_dims__(8, 1, 1) __launch_bounds__(256, 1)
lstm_kernel(const float* __restrict__ w_hh,   // layer base: [2][1024][256]
            const float* __restrict__ h0,     // [4][64][256]
            const float* __restrict__ c0,
            int layer)
{
    extern __shared__ float smem[];
    float* h_in = smem;                 // [2][8][HROW]
    float* scr  = smem + SCR_OFF;       // [8][32][36]

    float* y = layer ? g_y1 : g_y0;

    int bx  = blockIdx.x;
    int cid = bx >> 3;                   // 0..15
    int r   = bx & 7;                    // hd-chunk rank
    int dir = cid & 1;
    int bc  = cid >> 1;                  // batch chunk 0..7
    int tid = threadIdx.x;
    int kc  = tid >> 5;                  // warp = K-chunk (also epilogue batch)
    int hd  = tid & 31;                  // lane
    int hd_g = r * 32 + hd;
    int eb   = kc;                       // epilogue batch within chunk
    int b_g  = bc * 8 + eb;

    // ---- W block into registers: Wr[g][j] = w_hh[dir][g*256+hd_g][kc*32+j*4..+4) ----
    const float* Wd = w_hh + (size_t)dir * 1024 * 256;
    float4 Wr[4][8];
    #pragma unroll
    for (int g = 0; g < 4; g++) {
        const float* rowp = Wd + (size_t)(g * 256 + hd_g) * 256 + kc * 32;
        #pragma unroll
        for (int j = 0; j < 8; j++) Wr[g][j] = *(const float4*)(rowp + j * 4);
    }

    // ---- initial h (parity 0) ----
    const float* h0d = h0 + ((size_t)(2 * layer + dir) * 64 + bc * 8) * 256;
    for (int i = tid; i < 2048; i += 256) {
        int b = i >> 8, k = i & 255;
        h_in[b * HROW + k] = h0d[b * 256 + k];
    }
    float c = c0[((size_t)(2 * layer + dir) * 64 + b_g) * 256 + hd_g];

    // local tx-mbarrier
    uint32_t smem_u32 = (uint32_t)__cvta_generic_to_shared(smem);
    uint32_t mbar_l   = smem_u32 + MBAR_F * 4;
    if (tid == 0)
        asm volatile("mbarrier.init.shared.b64 [%0], 1;" :: "r"(mbar_l) : "memory");
    __syncthreads();
    asm volatile("barrier.cluster.arrive.aligned;" ::: "memory");
    asm volatile("barrier.cluster.wait.aligned;"   ::: "memory");

    // remote addresses for h delivery: slot [parity][eb][hd_g] in every rank
    uint32_t dst0 = smem_u32 + (uint32_t)((eb * HROW + hd_g) * 4);
    uint32_t rka[8], rmb[8];
    #pragma unroll
    for (int rk = 0; rk < 8; rk++) {
        asm("mapa.shared::cluster.u32 %0, %1, %2;" : "=r"(rka[rk]) : "r"(dst0),   "r"(rk));
        asm("mapa.shared::cluster.u32 %0, %1, %2;" : "=r"(rmb[rk]) : "r"(mbar_l), "r"(rk));
    }
    const uint32_t PAR_BYTES = (uint32_t)(HPARF * 4);

    float* scr_w = scr + hd * SCRROW + kc;              // + (b*32*SCRROW) + g*8
    const float* scr_r = scr + (eb * 32 + hd) * SCRROW; // epilogue read base

    for (int s = 0; s < 256; s++) {
        int t  = dir ? (255 - s) : s;
        int p  = s & 1;
        int wp = p ^ 1;

        // arm this step's phase: 1 arrive + 8192 tx bytes expected
        if (tid == 0 && s < 255)
            asm volatile("mbarrier.arrive.expect_tx.shared.b64 _, [%0], 8192;"
                         :: "r"(mbar_l) : "memory");

        // prefetch input-gate preacts for epilogue identity (hd_g, b_g)
        size_t xb = ((size_t)t * 64 + b_g) * 2048 + (size_t)dir * 1024 + hd_g;
        float xg0 = g_xg[xb];
        float xg1 = g_xg[xb + 256];
        float xg2 = g_xg[xb + 512];
        float xg3 = g_xg[xb + 768];

        // ---- partial dots: 4 gates x 8 batches over K-chunk [kc*32, kc*32+32) ----
        const float* hp = h_in + p * HPARF + kc * 32;
        unsigned long long acc[4][8];
        #pragma unroll
        for (int g = 0; g < 4; g++)
            #pragma unroll
            for (int b = 0; b < 8; b++) acc[g][b] = 0ull;

        #pragma unroll
        for (int j = 0; j < 8; j++) {
            #pragma unroll
            for (int b = 0; b < 8; b++) {
                float4 hv = *(const float4*)(hp + b * HROW + j * 4);   // broadcast
                ulonglong2 h2 = *(const ulonglong2*)&hv;
                #pragma unroll
                for (int g = 0; g < 4; g++) {
                    ulonglong2 w2 = *(const ulonglong2*)&Wr[g][j];
                    FMA2(acc[g][b], w2.x, h2.x);
                    FMA2(acc[g][b], w2.y, h2.y);
                }
            }
        }

        // fold f32x2 halves, stash partials in scratch
        #pragma unroll
        for (int g = 0; g < 4; g++)
            #pragma unroll
            for (int b = 0; b < 8; b++) {
                unsigned int lo, hi;
                UNPK2(lo, hi, acc[g][b]);
                scr_w[b * 32 * SCRROW + g * 8] = __uint_as_float(lo) + __uint_as_float(hi);
            }
        __syncthreads();

        // ---- epilogue for (hd_g, b_g): sum 8 kc-partials per gate ----
        float4 q0 = *(const float4*)(scr_r + 0);
        float4 q1 = *(const float4*)(scr_r + 4);
        float4 q2 = *(const float4*)(scr_r + 8);
        float4 q3 = *(const float4*)(scr_r + 12);
        float4 q4 = *(const float4*)(scr_r + 16);
        float4 q5 = *(const float4*)(scr_r + 20);
        float4 q6 = *(const float4*)(scr_r + 24);
        float4 q7 = *(const float4*)(scr_r + 28);
        float d0 = (q0.x + q0.y) + (q0.z + q0.w) + (q1.x + q1.y) + (q1.z + q1.w);
        float d1 = (q2.x + q2.y) + (q2.z + q2.w) + (q3.x + q3.y) + (q3.z + q3.w);
        float d2 = (q4.x + q4.y) + (q4.z + q4.w) + (q5.x + q5.y) + (q5.z + q5.w);
        float d3 = (q6.x + q6.y) + (q6.z + q6.w) + (q7.x + q7.y) + (q7.z + q7.w);

        float ig = sigf(d0 + xg0);
        float fg = sigf(d1 + xg1);
        float gg = tanhf(d2 + xg2);
        float og = sigf(d3 + xg3);
        c = fg * c + ig * gg;
        float h = og * tanhf(c);

        // layer output (fire-and-forget)
        y[((size_t)t * 64 + b_g) * 512 + (size_t)dir * 256 + hd_g] = h;

        if (s < 255) {
            // deliver h to all 8 cluster CTAs (4B tx each)
            uint32_t poff = wp ? PAR_BYTES : 0u;
            unsigned int hv = __float_as_uint(h);
            #pragma unroll
            for (int rk = 0; rk < 8; rk++)
                asm volatile(
                    "st.async.weak.shared::cluster.mbarrier::complete_tx::bytes.b32 [%0], %1, [%2];"
                    :: "r"(rka[rk] + poff), "r"(hv), "r"(rmb[rk]) : "memory");

            // wait for this step's phase (all 8KB delivered), acquire cluster
            unsigned int par = (unsigned int)(s & 1);
            asm volatile(
                "{\n\t"
                ".reg .pred P;\n\t"
                "WAIT_%=:\n\t"
                "mbarrier.try_wait.parity.acquire.cluster.shared::cta.b64 P, [%0], %1, 0x989680;\n\t"
                "@!P bra WAIT_%=;\n\t"
                "}"
                :: "r"(mbar_l), "r"(par) : "memory");
        }
    }
}

// ============================================================
// 4) hidden2tag
// ============================================================
__global__ void __launch_bounds__(256)
feats_kernel(const float* __restrict__ w_out, const float* __restrict__ b_out)
{
    __shared__ float ws[7 * 512];
    __shared__ float bs[7];
    int tid = threadIdx.x;
    for (int i = tid; i < 3584; i += 256) ws[i] = w_out[i];
    if (tid < 7) bs[tid] = b_out[tid];
    __syncthreads();

    int gw   = (blockIdx.x * 256 + tid) >> 5;
    int lane = tid & 31;
    int nw   = gridDim.x * 8;
    for (int m = gw; m < 16384; m += nw) {
        const float4* y4 = (const float4*)(g_y1 + (size_t)m * 512);
        float acc[7] = {0, 0, 0, 0, 0, 0, 0};
        #pragma unroll
        for (int q = 0; q < 4; q++) {
            int k4 = q * 32 + lane;
            float4 yv = y4[k4];
            #pragma unroll
            for (int tg = 0; tg < 7; tg++) {
                float4 wv = *(const float4*)(ws + tg * 512 + k4 * 4);
                acc[tg] += yv.x * wv.x + yv.y * wv.y + yv.z * wv.z + yv.w * wv.w;
            }
        }
        #pragma unroll
        for (int tg = 0; tg < 7; tg++) {
            #pragma unroll
            for (int off = 16; off; off >>= 1)
                acc[tg] += __shfl_xor_sync(0xFFFFFFFFu, acc[tg], off);
        }
        float v = acc[0];
        #pragma unroll
        for (int tg = 1; tg < 7; tg++) if (lane == tg) v = acc[tg];
        if (lane < 7) g_feats[m * 7 + lane] = v + bs[lane];
    }
}

// ============================================================
// 5) Viterbi: 1 CTA, thread = batch; packed backpointers in smem.
//    out = [path as float (B*T)] ++ [score (B)]
// ============================================================
__global__ void __launch_bounds__(64)
viterbi_kernel(const float* __restrict__ trans, float* __restrict__ out)
{
    extern __shared__ unsigned int bp_s[];   // [256][64]
    __shared__ float tr[49];
    int b = threadIdx.x;
    if (b < 49) tr[b] = trans[b];
    __syncthreads();

    float v[7];
    #pragma unroll
    for (int k = 0; k < 7; k++) v[k] = (k == 5) ? 0.0f : NEG_;  // START=5

    for (int t = 0; t < 256; t++) {
        const float* f = g_feats + ((size_t)t * 64 + b) * 7;
        float fv[7];
        #pragma unroll
        for (int k = 0; k < 7; k++) fv[k] = f[k];

        unsigned int word = 0;
        float nv[7];
        #pragma unroll
        for (int nx = 0; nx < 7; nx++) {
            float best = v[0] + tr[nx * 7 + 0];
            int arg = 0;
            #pragma unroll
            for (int pv = 1; pv < 7; pv++) {
                float sc = v[pv] + tr[nx * 7 + pv];
                if (sc > best) { best = sc; arg = pv; }
            }
            nv[nx] = best + fv[nx];
            word |= ((unsigned int)arg) << (3 * nx);
        }
        #pragma unroll
        for (int k = 0; k < 7; k++) v[k] = nv[k];
        bp_s[t * 64 + b] = word;
    }

    float best = v[0] + tr[6 * 7 + 0];
    int last = 0;
    #pragma unroll
    for (int k = 1; k < 7; k++) {
        float sc = v[k] + tr[6 * 7 + k];
        if (sc > best) { best = sc; last = k; }
    }
    out[16384 + b] = best;

    int tag = last;
    out[(size_t)b * 256 + 255] = (float)tag;
    for (int t = 254; t >= 0; t--) {
        unsigned int w = bp_s[(t + 1) * 64 + b];
        tag = (int)((w >> (3 * tag)) & 7u);
        out[(size_t)b * 256 + t] = (float)tag;
    }
}

// ============================================================
// launcher
// ============================================================
extern "C" void kernel_launch(void* const* d_in, const int* in_sizes, int n_in,
                              void* d_out, int out_size)
{
    (void)in_sizes; (void)n_in; (void)out_size;
    const int*   sent  = (const int*)  d_in[0];
    const float* emb   = (const float*)d_in[1];
    const float* w_ih  = (const float*)d_in[2];
    const float* w_hh  = (const float*)d_in[3];
    const float* b_ih  = (const float*)d_in[4];
    const float* b_hh  = (const float*)d_in[5];
    const float* w_out = (const float*)d_in[6];
    const float* b_out = (const float*)d_in[7];
    const float* trans = (const float*)d_in[8];
    const float* h0    = (const float*)d_in[9];
    const float* c0    = (const float*)d_in[10];
    float* out = (float*)d_out;

    cudaFuncSetAttribute(lstm_kernel, cudaFuncAttributeMaxDynamicSharedMemorySize,
                         LSTM_SMEM_BYTES);
    cudaFuncSetAttribute(viterbi_kernel, cudaFuncAttributeMaxDynamicSharedMemorySize,
                         VIT_SMEM_BYTES);

    embed_kernel<<<256, 256>>>(sent, emb);
    for (int l = 0; l < 2; l++) {
        gemm_kernel<<<dim3(16, 128), 256>>>(w_ih + (size_t)l * 2048 * 512,
                                            b_ih + l * 2048,
                                            b_hh + l * 2048, l);
        lstm_kernel<<<128, 256, LSTM_SMEM_BYTES>>>(w_hh + (size_t)l * 2 * 1024 * 256,
                                                   h0, c0, l);
    }
    feats_kernel<<<256, 256>>>(w_out, b_out);
    viterbi_kernel<<<1, 64, VIT_SMEM_BYTES>>>(trans, out);
}